// round 4
// baseline (speedup 1.0000x reference)
#include <cuda_runtime.h>
#include <cstdint>

// Problem dims (fixed)
#define NN 10000
#define NE 100000
#define OD 12
#define CD 128
#define KD 32
#define AD 16
#define CAD 144
#define ROWS (NN*OD)          // 120000
#define NOC  (NN*OD*CD)       // 15360000
#define K1_TILES (ROWS/32)    // 3750

// Scratch (device globals: allocation-free rule)
__device__ __align__(16) float g_y [NOC];
__device__ __align__(16) float g_x1[NOC];
__device__ float g_fk[OD*OD*CD];
__device__ int   g_cnt[NN];
__device__ int   g_cur[NN];
__device__ int   g_off[NN];
__device__ int   g_elist[NE];   // packed (src<<17)|e

// ---------------------------------------------------------------------------
// CSR build.  edge_index is int32: row0 = src[E], row1 = dst[E].
// ---------------------------------------------------------------------------
__global__ void k_zero_cnt() {
    int i = blockIdx.x*blockDim.x + threadIdx.x;
    if (i < NN) { g_cnt[i] = 0; g_cur[i] = 0; }
}

__global__ void k_count(const int* __restrict__ eidx) {
    for (int e = blockIdx.x*blockDim.x + threadIdx.x; e < NE; e += gridDim.x*blockDim.x) {
        int dst = eidx[NE + e];
        atomicAdd(&g_cnt[dst], 1);
    }
}

// single block, 1024 threads, 10 elements per thread
__global__ void __launch_bounds__(1024) k_scan() {
    __shared__ int ps[1024];
    int t = threadIdx.x;
    int loc[10];
    int sum = 0;
#pragma unroll
    for (int i = 0; i < 10; ++i) {
        int idx = t*10 + i;
        int v = (idx < NN) ? g_cnt[idx] : 0;
        loc[i] = sum;       // exclusive within chunk
        sum += v;
    }
    ps[t] = sum;
    __syncthreads();
    // Hillis-Steele inclusive scan over 1024 partials
    for (int off = 1; off < 1024; off <<= 1) {
        int v = (t >= off) ? ps[t - off] : 0;
        __syncthreads();
        ps[t] += v;
        __syncthreads();
    }
    int base = ps[t] - sum;   // exclusive prefix of this chunk
#pragma unroll
    for (int i = 0; i < 10; ++i) {
        int idx = t*10 + i;
        if (idx < NN) g_off[idx] = base + loc[i];
    }
}

__global__ void k_fill(const int* __restrict__ eidx) {
    for (int e = blockIdx.x*blockDim.x + threadIdx.x; e < NE; e += gridDim.x*blockDim.x) {
        int src = eidx[e];
        int dst = eidx[NE + e];
        int pos = g_off[dst] + atomicAdd(&g_cur[dst], 1);
        g_elist[pos] = (src << 17) | e;
    }
}

// ---------------------------------------------------------------------------
// K0: fiber kernel precompute  g_fk[p*O+o][c] = sum_k fkb[p,o,k] * Wf[c,k]
// ---------------------------------------------------------------------------
__global__ void k_fiber_pre(const float* __restrict__ fkb,
                            const float* __restrict__ Wf) {
    __shared__ float wfs[CD*KD];
    __shared__ float fb[KD];
    int tid = threadIdx.x;
    for (int i = tid; i < CD*KD; i += blockDim.x) wfs[i] = Wf[i];
    int po = blockIdx.x;
    if (tid < KD) fb[tid] = fkb[po*KD + tid];
    __syncthreads();
    int c = tid;
    float acc = 0.f;
#pragma unroll
    for (int k = 0; k < KD; ++k) acc += fb[k] * wfs[c*KD + k];
    g_fk[po*CD + c] = acc;
}

// ---------------------------------------------------------------------------
// K1: y[row][co] = sum_ci x[row][ci] * Wpre[co][ci]   (row = n*O+o)
// 256 threads, tile = 32 rows x 128 cols, k=128 fully resident.
// ---------------------------------------------------------------------------
#define K1_SMEM ((128*132 + 128*36)*4)

__global__ void __launch_bounds__(256) k_node_pre(const float* __restrict__ x,
                                                  const float* __restrict__ Wpre) {
    extern __shared__ float sm[];
    float* Ws = sm;               // [ci][co], pitch 132
    float* xs = sm + 128*132;     // [ci][r],  pitch 36
    int tid = threadIdx.x;

    for (int idx = tid; idx < CD*CD; idx += 256) {
        int co = idx >> 7, ci = idx & 127;
        Ws[ci*132 + co] = Wpre[co*CAD + ci];
    }

    int lane = tid & 31, warp = tid >> 5;
    for (int tile = blockIdx.x; tile < K1_TILES; tile += gridDim.x) {
        int rowBase = tile*32;
        __syncthreads();
        for (int idx = tid; idx < 32*CD; idx += 256) {
            int r = idx >> 7, ci = idx & 127;
            xs[ci*36 + r] = x[(size_t)(rowBase + r)*CD + ci];
        }
        __syncthreads();

        float acc[4][4];
#pragma unroll
        for (int r = 0; r < 4; ++r)
#pragma unroll
            for (int q = 0; q < 4; ++q) acc[r][q] = 0.f;

#pragma unroll 8
        for (int ci = 0; ci < CD; ++ci) {
            float4 xv = *(const float4*)&xs[ci*36  + warp*4];
            float4 wv = *(const float4*)&Ws[ci*132 + lane*4];
            acc[0][0] += xv.x*wv.x; acc[0][1] += xv.x*wv.y; acc[0][2] += xv.x*wv.z; acc[0][3] += xv.x*wv.w;
            acc[1][0] += xv.y*wv.x; acc[1][1] += xv.y*wv.y; acc[1][2] += xv.y*wv.z; acc[1][3] += xv.y*wv.w;
            acc[2][0] += xv.z*wv.x; acc[2][1] += xv.z*wv.y; acc[2][2] += xv.z*wv.z; acc[2][3] += xv.z*wv.w;
            acc[3][0] += xv.w*wv.x; acc[3][1] += xv.w*wv.y; acc[3][2] += xv.w*wv.z; acc[3][3] += xv.w*wv.w;
        }
#pragma unroll
        for (int r = 0; r < 4; ++r) {
            float4 o4 = make_float4(acc[r][0], acc[r][1], acc[r][2], acc[r][3]);
            *(float4*)&g_y[(size_t)(rowBase + warp*4 + r)*CD + lane*4] = o4;
        }
    }
}

// ---------------------------------------------------------------------------
// K2: gather kernel. One CTA per destination node. 256 threads:
//   c = tid&127, oh = tid>>7, each thread accumulates 6 of 12 orientations.
// ---------------------------------------------------------------------------
__global__ void __launch_bounds__(256) k_gather(const float* __restrict__ kb,
                                                const float* __restrict__ attr,
                                                const float* __restrict__ Wpre,
                                                const float* __restrict__ Wk) {
    __shared__ __align__(16) float wkt[KD*CD];     // [k][c]
    __shared__ __align__(16) float wat[AD*CD];     // [a][c]
    __shared__ __align__(16) float kb_s[OD*KD];
    __shared__ __align__(16) float at_s[OD*AD];

    int tid = threadIdx.x;
    for (int i = tid; i < KD*CD; i += 256) {
        int cc = i >> 5, k = i & 31;
        wkt[k*CD + cc] = Wk[i];
    }
    for (int i = tid; i < AD*CD; i += 256) {
        int cc = i >> 4, a = i & 15;
        wat[a*CD + cc] = Wpre[cc*CAD + CD + a];
    }
    __syncthreads();

    int c = tid & 127, oh = tid >> 7;
    float wk[KD], wa[AD];
#pragma unroll
    for (int k = 0; k < KD; ++k) wk[k] = wkt[k*CD + c];
#pragma unroll
    for (int a = 0; a < AD; ++a) wa[a] = wat[a*CD + c];

    int n = blockIdx.x;
    int r0 = g_off[n];
    int r1 = r0 + g_cnt[n];

    float acc[6];
#pragma unroll
    for (int j = 0; j < 6; ++j) acc[j] = 0.f;

    for (int it = r0; it < r1; ++it) {
        int pk = g_elist[it];
        int e   = pk & 131071;
        int src = pk >> 17;

        __syncthreads();   // previous iteration's reads of kb_s/at_s done
        const float* kbp = kb + (size_t)e*(OD*KD);
        for (int i = tid; i < OD*KD; i += 256) kb_s[i] = kbp[i];
        const float* atp = attr + (size_t)e*(OD*AD);
        if (tid < OD*AD) at_s[tid] = atp[tid];
        __syncthreads();

        const float* yb = g_y + (size_t)src*(OD*CD) + c;
#pragma unroll
        for (int j = 0; j < 6; ++j) {
            int o = oh + 2*j;
            float km = 0.f, z = 0.f;
            const float4* k4 = (const float4*)(kb_s + o*KD);
#pragma unroll
            for (int q = 0; q < 8; ++q) {
                float4 v = k4[q];
                km += v.x*wk[4*q] + v.y*wk[4*q+1] + v.z*wk[4*q+2] + v.w*wk[4*q+3];
            }
            const float4* a4 = (const float4*)(at_s + o*AD);
#pragma unroll
            for (int q = 0; q < 4; ++q) {
                float4 v = a4[q];
                z += v.x*wa[4*q] + v.y*wa[4*q+1] + v.z*wa[4*q+2] + v.w*wa[4*q+3];
            }
            float yv = yb[o*CD];
            acc[j] += (yv + z) * km;
        }
    }

#pragma unroll
    for (int j = 0; j < 6; ++j) {
        int o = oh + 2*j;
        g_x1[(size_t)n*(OD*CD) + o*CD + c] = acc[j];
    }
}

// ---------------------------------------------------------------------------
// K3: out[n,p,c] = (sum_o x1[n,o,c] * fk[p,o,c]) / O + bias[c]
// ---------------------------------------------------------------------------
#define K3_SMEM (OD*OD*CD*4)

__global__ void __launch_bounds__(256) k_fiber(const float* __restrict__ bias,
                                               float* __restrict__ out) {
    extern __shared__ float fks[];
    int tid = threadIdx.x;
    for (int i = tid; i < OD*OD*CD; i += blockDim.x) fks[i] = g_fk[i];
    __syncthreads();
    int c = tid & 127, sub = tid >> 7;
    float bs = bias[c];
    int base = blockIdx.x * 8;
    for (int nn = sub; nn < 8; nn += 2) {
        int n = base + nn;
        if (n >= NN) break;
        float xr[OD];
#pragma unroll
        for (int o = 0; o < OD; ++o)
            xr[o] = g_x1[(size_t)(n*OD + o)*CD + c];
#pragma unroll
        for (int p = 0; p < OD; ++p) {
            float acc = 0.f;
#pragma unroll
            for (int o = 0; o < OD; ++o)
                acc += xr[o] * fks[(p*OD + o)*CD + c];
            out[(size_t)(n*OD + p)*CD + c] = acc * (1.0f/12.0f) + bs;
        }
    }
}

// ---------------------------------------------------------------------------
extern "C" void kernel_launch(void* const* d_in, const int* in_sizes, int n_in,
                              void* d_out, int out_size) {
    (void)out_size;
    // Size-based dispatch (robust to metadata ordering). Unique element counts:
    //   x:15360000  kb:38400000  fkb:4608  eidx:200000  attr:19200000
    //   Wpre:18432  Wk:4096(first)  Wf:4096(second)  bias:128
    const float *x=0, *kb=0, *fkb=0, *attr=0, *Wpre=0, *Wk=0, *Wf=0, *bias=0;
    const int* eidx = 0;
    for (int i = 0; i < n_in; ++i) {
        switch (in_sizes[i]) {
            case 15360000: x    = (const float*)d_in[i]; break;
            case 38400000: kb   = (const float*)d_in[i]; break;
            case 4608:     fkb  = (const float*)d_in[i]; break;
            case 200000:   eidx = (const int*)  d_in[i]; break;
            case 19200000: attr = (const float*)d_in[i]; break;
            case 18432:    Wpre = (const float*)d_in[i]; break;
            case 4096:     if (!Wk) Wk = (const float*)d_in[i];
                           else     Wf = (const float*)d_in[i]; break;
            case 128:      bias = (const float*)d_in[i]; break;
            default: break;
        }
    }
    float* out = (float*)d_out;

    cudaFuncSetAttribute(k_node_pre, cudaFuncAttributeMaxDynamicSharedMemorySize, K1_SMEM);
    cudaFuncSetAttribute(k_fiber,    cudaFuncAttributeMaxDynamicSharedMemorySize, K3_SMEM);

    k_zero_cnt <<<(NN + 255)/256, 256>>>();
    k_count    <<<256, 256>>>(eidx);
    k_scan     <<<1, 1024>>>();
    k_fill     <<<256, 256>>>(eidx);
    k_fiber_pre<<<OD*OD, CD>>>(fkb, Wf);
    k_node_pre <<<592, 256, K1_SMEM>>>(x, Wpre);
    k_gather   <<<NN, 256>>>(kb, attr, Wpre, Wk);
    k_fiber    <<<(NN + 7)/8, 256, K3_SMEM>>>(bias, out);
}

// round 6
// speedup vs baseline: 1.5899x; 1.5899x over previous
#include <cuda_runtime.h>
#include <cstdint>

// Problem dims (fixed)
#define NN 10000
#define NE 100000
#define OD 12
#define CD 128
#define KD 32
#define AD 16
#define CAD 144
#define ROWS (NN*OD)          // 120000
#define NOC  (NN*OD*CD)       // 15360000
#define K1_TILES (ROWS/32)    // 3750

typedef unsigned long long ull;

// f32x2 packed-math helpers (Blackwell FFMA2 via PTX)
__device__ __forceinline__ void ffma2(ull& d, ull a, ull b) {
    asm("fma.rn.f32x2 %0, %1, %2, %0;" : "+l"(d) : "l"(a), "l"(b));
}
__device__ __forceinline__ ull pack2(float lo, float hi) {
    ull d; asm("mov.b64 %0, {%1, %2};" : "=l"(d) : "f"(lo), "f"(hi)); return d;
}
__device__ __forceinline__ float hsum2(ull v) {
    float lo, hi; asm("mov.b64 {%0, %1}, %2;" : "=f"(lo), "=f"(hi) : "l"(v));
    return lo + hi;
}
__device__ __forceinline__ void unpack2(ull v, float& lo, float& hi) {
    asm("mov.b64 {%0, %1}, %2;" : "=f"(lo), "=f"(hi) : "l"(v));
}

// Scratch (device globals: allocation-free rule)
__device__ __align__(16) float g_y [NOC];
__device__ __align__(16) float g_x1[NOC];
__device__ float g_fk[OD*OD*CD];
__device__ int   g_cnt[NN];
__device__ int   g_cur[NN];
__device__ int   g_off[NN];
__device__ int   g_elist[NE];   // packed (src<<17)|e

// ---------------------------------------------------------------------------
// CSR build.  edge_index is int32: row0 = src[E], row1 = dst[E].
// ---------------------------------------------------------------------------
__global__ void k_zero_cnt() {
    int i = blockIdx.x*blockDim.x + threadIdx.x;
    if (i < NN) { g_cnt[i] = 0; g_cur[i] = 0; }
}

__global__ void k_count(const int* __restrict__ eidx) {
    for (int e = blockIdx.x*blockDim.x + threadIdx.x; e < NE; e += gridDim.x*blockDim.x) {
        int dst = eidx[NE + e];
        atomicAdd(&g_cnt[dst], 1);
    }
}

__global__ void __launch_bounds__(1024) k_scan() {
    __shared__ int ps[1024];
    int t = threadIdx.x;
    int loc[10];
    int sum = 0;
#pragma unroll
    for (int i = 0; i < 10; ++i) {
        int idx = t*10 + i;
        int v = (idx < NN) ? g_cnt[idx] : 0;
        loc[i] = sum;
        sum += v;
    }
    ps[t] = sum;
    __syncthreads();
    for (int off = 1; off < 1024; off <<= 1) {
        int v = (t >= off) ? ps[t - off] : 0;
        __syncthreads();
        ps[t] += v;
        __syncthreads();
    }
    int base = ps[t] - sum;
#pragma unroll
    for (int i = 0; i < 10; ++i) {
        int idx = t*10 + i;
        if (idx < NN) g_off[idx] = base + loc[i];
    }
}

__global__ void k_fill(const int* __restrict__ eidx) {
    for (int e = blockIdx.x*blockDim.x + threadIdx.x; e < NE; e += gridDim.x*blockDim.x) {
        int src = eidx[e];
        int dst = eidx[NE + e];
        int pos = g_off[dst] + atomicAdd(&g_cur[dst], 1);
        g_elist[pos] = (src << 17) | e;
    }
}

// ---------------------------------------------------------------------------
// K0: fiber kernel precompute
// ---------------------------------------------------------------------------
__global__ void k_fiber_pre(const float* __restrict__ fkb,
                            const float* __restrict__ Wf) {
    __shared__ float wfs[CD*KD];
    __shared__ float fb[KD];
    int tid = threadIdx.x;
    for (int i = tid; i < CD*KD; i += blockDim.x) wfs[i] = Wf[i];
    int po = blockIdx.x;
    if (tid < KD) fb[tid] = fkb[po*KD + tid];
    __syncthreads();
    int c = tid;
    float acc = 0.f;
#pragma unroll
    for (int k = 0; k < KD; ++k) acc += fb[k] * wfs[c*KD + k];
    g_fk[po*CD + c] = acc;
}

// ---------------------------------------------------------------------------
// K1: y[row][co] = sum_ci x[row][ci] * Wpre[co][ci]   — f32x2 over co-pairs
// ---------------------------------------------------------------------------
#define K1_SMEM ((128*132 + 128*36)*4)

__global__ void __launch_bounds__(256) k_node_pre(const float* __restrict__ x,
                                                  const float* __restrict__ Wpre) {
    extern __shared__ float sm[];
    float* Ws = sm;               // [ci][co], pitch 132
    float* xs = sm + 128*132;     // [ci][r],  pitch 36
    int tid = threadIdx.x;

    for (int idx = tid; idx < CD*CD; idx += 256) {
        int co = idx >> 7, ci = idx & 127;
        Ws[ci*132 + co] = Wpre[co*CAD + ci];
    }

    int lane = tid & 31, warp = tid >> 5;
    for (int tile = blockIdx.x; tile < K1_TILES; tile += gridDim.x) {
        int rowBase = tile*32;
        __syncthreads();
        for (int idx = tid; idx < 32*CD; idx += 256) {
            int r = idx >> 7, ci = idx & 127;
            xs[ci*36 + r] = x[(size_t)(rowBase + r)*CD + ci];
        }
        __syncthreads();

        ull acc2[4][2];
#pragma unroll
        for (int r = 0; r < 4; ++r) { acc2[r][0] = 0ull; acc2[r][1] = 0ull; }

#pragma unroll 8
        for (int ci = 0; ci < CD; ++ci) {
            float4 xv = *(const float4*)&xs[ci*36  + warp*4];
            const ulonglong2* wp = (const ulonglong2*)&Ws[ci*132 + lane*4];
            ulonglong2 w = *wp;
            ull xd;
            xd = pack2(xv.x, xv.x); ffma2(acc2[0][0], xd, w.x); ffma2(acc2[0][1], xd, w.y);
            xd = pack2(xv.y, xv.y); ffma2(acc2[1][0], xd, w.x); ffma2(acc2[1][1], xd, w.y);
            xd = pack2(xv.z, xv.z); ffma2(acc2[2][0], xd, w.x); ffma2(acc2[2][1], xd, w.y);
            xd = pack2(xv.w, xv.w); ffma2(acc2[3][0], xd, w.x); ffma2(acc2[3][1], xd, w.y);
        }
#pragma unroll
        for (int r = 0; r < 4; ++r) {
            float4 o4;
            unpack2(acc2[r][0], o4.x, o4.y);
            unpack2(acc2[r][1], o4.z, o4.w);
            *(float4*)&g_y[(size_t)(rowBase + warp*4 + r)*CD + lane*4] = o4;
        }
    }
}

// ---------------------------------------------------------------------------
// K2: gather kernel.  One CTA per destination node, 128 threads.
//   Thread owns channel c = tid, computes all 12 orientations.
//   f32x2 dot products for km (over k) and z (over a).
//   Software-pipelined edge staging.
// ---------------------------------------------------------------------------
__global__ void __launch_bounds__(128) k_gather(const float* __restrict__ kb,
                                                const float* __restrict__ attr,
                                                const float* __restrict__ Wpre,
                                                const float* __restrict__ Wk) {
    // double-buffered edge data: [0:384) kb rows (o*32+k), [384:576) attr (o*16+a)
    __shared__ __align__(16) float sbuf[2][576];

    int tid = threadIdx.x;          // channel c
    int c = tid;

    // per-channel weight pairs in registers
    ull wk2[KD/2], wa2[AD/2];
    {
        const float2* wkp = (const float2*)(Wk + (size_t)c*KD);
#pragma unroll
        for (int i = 0; i < KD/2; ++i) { float2 v = wkp[i]; wk2[i] = pack2(v.x, v.y); }
        const float2* wap = (const float2*)(Wpre + (size_t)c*CAD + CD);
#pragma unroll
        for (int i = 0; i < AD/2; ++i) { float2 v = wap[i]; wa2[i] = pack2(v.x, v.y); }
    }

    int n  = blockIdx.x;
    int r0 = g_off[n];
    int cnt = g_cnt[n];
    int r1 = r0 + cnt;

    float acc[OD];
#pragma unroll
    for (int o = 0; o < OD; ++o) acc[o] = 0.f;

    if (cnt > 0) {
        int pk = g_elist[r0];
        {   // stage first edge directly
            int e = pk & 0x1FFFF;
            for (int i = tid; i < 576; i += 128)
                sbuf[0][i] = (i < 384) ? kb[(size_t)e*384 + i]
                                       : attr[(size_t)e*192 + (i - 384)];
        }
        __syncthreads();

        for (int it = r0; it < r1; ++it) {
            int cur = (it - r0) & 1;
            int src = pk >> 17;

            // ---- prefetch next edge into registers (overlaps with compute) ----
            bool hasn = (it + 1 < r1);
            int pkn = 0;
            float pf0 = 0.f, pf1 = 0.f, pf2 = 0.f, pf3 = 0.f, pf4 = 0.f;
            if (hasn) {
                pkn = g_elist[it + 1];
                int e = pkn & 0x1FFFF;
                const float* kbe = kb   + (size_t)e*384;
                const float* ate = attr + (size_t)e*192;
                pf0 = kbe[tid];
                pf1 = kbe[tid + 128];
                pf2 = kbe[tid + 256];
                pf3 = ate[tid];                        // attr[0..127]
                if (tid < 64) pf4 = ate[tid + 128];    // attr[128..191]  (FIXED)
            }

            // ---- gather y for all orientations (MLP 12) ----
            const float* yb = g_y + (size_t)src*(OD*CD) + c;
            float yv[OD];
#pragma unroll
            for (int o = 0; o < OD; ++o) yv[o] = yb[o*CD];

            // ---- compute ----
            const float* kbb = sbuf[cur];
            const float* atb = sbuf[cur] + 384;
#pragma unroll
            for (int o = 0; o < OD; ++o) {
                ull a2 = 0ull;
                const ulonglong2* k2 = (const ulonglong2*)(kbb + o*KD);
#pragma unroll
                for (int q = 0; q < 8; ++q) {
                    ulonglong2 v = k2[q];
                    ffma2(a2, v.x, wk2[2*q]);
                    ffma2(a2, v.y, wk2[2*q+1]);
                }
                ull z2 = 0ull;
                const ulonglong2* t2 = (const ulonglong2*)(atb + o*AD);
#pragma unroll
                for (int q = 0; q < 4; ++q) {
                    ulonglong2 v = t2[q];
                    ffma2(z2, v.x, wa2[2*q]);
                    ffma2(z2, v.y, wa2[2*q+1]);
                }
                float km = hsum2(a2);
                float z  = hsum2(z2);
                acc[o] += (yv[o] + z) * km;
            }

            // ---- commit prefetched data to the other buffer ----
            if (hasn) {
                int nxt = cur ^ 1;
                sbuf[nxt][tid]       = pf0;
                sbuf[nxt][tid + 128] = pf1;
                sbuf[nxt][tid + 256] = pf2;
                sbuf[nxt][tid + 384] = pf3;
                if (tid < 64) sbuf[nxt][tid + 512] = pf4;
            }
            __syncthreads();
            pk = pkn;
        }
    }

#pragma unroll
    for (int o = 0; o < OD; ++o)
        g_x1[(size_t)n*(OD*CD) + o*CD + c] = acc[o];
}

// ---------------------------------------------------------------------------
// K3: out[n,p,c] = (sum_o x1[n,o,c] * fk[p,o,c]) / O + bias[c]
// ---------------------------------------------------------------------------
#define K3_SMEM (OD*OD*CD*4)

__global__ void __launch_bounds__(256) k_fiber(const float* __restrict__ bias,
                                               float* __restrict__ out) {
    extern __shared__ float fks[];
    int tid = threadIdx.x;
    for (int i = tid; i < OD*OD*CD; i += blockDim.x) fks[i] = g_fk[i];
    __syncthreads();
    int c = tid & 127, sub = tid >> 7;
    float bs = bias[c];
    int base = blockIdx.x * 8;
    for (int nn = sub; nn < 8; nn += 2) {
        int n = base + nn;
        if (n >= NN) break;
        float xr[OD];
#pragma unroll
        for (int o = 0; o < OD; ++o)
            xr[o] = g_x1[(size_t)(n*OD + o)*CD + c];
#pragma unroll
        for (int p = 0; p < OD; ++p) {
            float acc = 0.f;
#pragma unroll
            for (int o = 0; o < OD; ++o)
                acc += xr[o] * fks[(p*OD + o)*CD + c];
            out[(size_t)(n*OD + p)*CD + c] = acc * (1.0f/12.0f) + bs;
        }
    }
}

// ---------------------------------------------------------------------------
extern "C" void kernel_launch(void* const* d_in, const int* in_sizes, int n_in,
                              void* d_out, int out_size) {
    (void)out_size;
    // Size-based dispatch. Unique element counts except Wk/Wf (4096, order tiebreak).
    const float *x=0, *kb=0, *fkb=0, *attr=0, *Wpre=0, *Wk=0, *Wf=0, *bias=0;
    const int* eidx = 0;
    for (int i = 0; i < n_in; ++i) {
        switch (in_sizes[i]) {
            case 15360000: x    = (const float*)d_in[i]; break;
            case 38400000: kb   = (const float*)d_in[i]; break;
            case 4608:     fkb  = (const float*)d_in[i]; break;
            case 200000:   eidx = (const int*)  d_in[i]; break;
            case 19200000: attr = (const float*)d_in[i]; break;
            case 18432:    Wpre = (const float*)d_in[i]; break;
            case 4096:     if (!Wk) Wk = (const float*)d_in[i];
                           else     Wf = (const float*)d_in[i]; break;
            case 128:      bias = (const float*)d_in[i]; break;
            default: break;
        }
    }
    float* out = (float*)d_out;

    cudaFuncSetAttribute(k_node_pre, cudaFuncAttributeMaxDynamicSharedMemorySize, K1_SMEM);
    cudaFuncSetAttribute(k_fiber,    cudaFuncAttributeMaxDynamicSharedMemorySize, K3_SMEM);

    k_zero_cnt <<<(NN + 255)/256, 256>>>();
    k_count    <<<256, 256>>>(eidx);
    k_scan     <<<1, 1024>>>();
    k_fill     <<<256, 256>>>(eidx);
    k_fiber_pre<<<OD*OD, CD>>>(fkb, Wf);
    k_node_pre <<<592, 256, K1_SMEM>>>(x, Wpre);
    k_gather   <<<NN, 128>>>(kb, attr, Wpre, Wk);
    k_fiber    <<<(NN + 7)/8, 256, K3_SMEM>>>(bias, out);
}

// round 9
// speedup vs baseline: 1.6429x; 1.0333x over previous
#include <cuda_runtime.h>
#include <cstdint>

// Problem dims (fixed)
#define NN 10000
#define NE 100000
#define OD 12
#define CD 128
#define KD 32
#define AD 16
#define CAD 144
#define ROWS (NN*OD)          // 120000
#define NOC  (NN*OD*CD)       // 15360000
#define K1_TILES (ROWS/32)    // 3750

typedef unsigned long long ull;

// f32x2 packed-math helpers (Blackwell FFMA2 via PTX)
__device__ __forceinline__ void ffma2(ull& d, ull a, ull b) {
    asm("fma.rn.f32x2 %0, %1, %2, %0;" : "+l"(d) : "l"(a), "l"(b));
}
__device__ __forceinline__ ull pack2(float lo, float hi) {
    ull d; asm("mov.b64 %0, {%1, %2};" : "=l"(d) : "f"(lo), "f"(hi)); return d;
}
__device__ __forceinline__ float hsum2(ull v) {
    float lo, hi; asm("mov.b64 {%0, %1}, %2;" : "=f"(lo), "=f"(hi) : "l"(v));
    return lo + hi;
}
__device__ __forceinline__ void unpack2(ull v, float& lo, float& hi) {
    asm("mov.b64 {%0, %1}, %2;" : "=f"(lo), "=f"(hi) : "l"(v));
}
__device__ __forceinline__ void cp_async16(unsigned smem_addr, const void* gptr) {
    asm volatile("cp.async.cg.shared.global [%0], [%1], 16;"
                 :: "r"(smem_addr), "l"(gptr) : "memory");
}

// Scratch (device globals: allocation-free rule)
__device__ __align__(16) float g_y [NOC];
__device__ __align__(16) float g_x1[NOC];
__device__ float g_fk[OD*OD*CD];
__device__ int   g_cnt[NN];
__device__ int   g_cur[NN];
__device__ int   g_off[NN];
__device__ int   g_elist[NE];   // packed (src<<17)|e

// ---------------------------------------------------------------------------
// CSR build.  edge_index is int32: row0 = src[E], row1 = dst[E].
// ---------------------------------------------------------------------------
__global__ void k_zero_cnt() {
    int i = blockIdx.x*blockDim.x + threadIdx.x;
    if (i < NN) { g_cnt[i] = 0; g_cur[i] = 0; }
}

__global__ void k_count(const int* __restrict__ eidx) {
    for (int e = blockIdx.x*blockDim.x + threadIdx.x; e < NE; e += gridDim.x*blockDim.x) {
        int dst = eidx[NE + e];
        atomicAdd(&g_cnt[dst], 1);
    }
}

__global__ void __launch_bounds__(1024) k_scan() {
    __shared__ int ps[1024];
    int t = threadIdx.x;
    int loc[10];
    int sum = 0;
#pragma unroll
    for (int i = 0; i < 10; ++i) {
        int idx = t*10 + i;
        int v = (idx < NN) ? g_cnt[idx] : 0;
        loc[i] = sum;
        sum += v;
    }
    ps[t] = sum;
    __syncthreads();
    for (int off = 1; off < 1024; off <<= 1) {
        int v = (t >= off) ? ps[t - off] : 0;
        __syncthreads();
        ps[t] += v;
        __syncthreads();
    }
    int base = ps[t] - sum;
#pragma unroll
    for (int i = 0; i < 10; ++i) {
        int idx = t*10 + i;
        if (idx < NN) g_off[idx] = base + loc[i];
    }
}

__global__ void k_fill(const int* __restrict__ eidx) {
    for (int e = blockIdx.x*blockDim.x + threadIdx.x; e < NE; e += gridDim.x*blockDim.x) {
        int src = eidx[e];
        int dst = eidx[NE + e];
        int pos = g_off[dst] + atomicAdd(&g_cur[dst], 1);
        g_elist[pos] = (src << 17) | e;
    }
}

// ---------------------------------------------------------------------------
// K0: fiber kernel precompute
// ---------------------------------------------------------------------------
__global__ void k_fiber_pre(const float* __restrict__ fkb,
                            const float* __restrict__ Wf) {
    __shared__ float wfs[CD*KD];
    __shared__ float fb[KD];
    int tid = threadIdx.x;
    for (int i = tid; i < CD*KD; i += blockDim.x) wfs[i] = Wf[i];
    int po = blockIdx.x;
    if (tid < KD) fb[tid] = fkb[po*KD + tid];
    __syncthreads();
    int c = tid;
    float acc = 0.f;
#pragma unroll
    for (int k = 0; k < KD; ++k) acc += fb[k] * wfs[c*KD + k];
    g_fk[po*CD + c] = acc;
}

// ---------------------------------------------------------------------------
// K1: y[row][co] = sum_ci x[row][ci] * Wpre[co][ci]   — f32x2 over co-pairs
// ---------------------------------------------------------------------------
#define K1_SMEM ((128*132 + 128*36)*4)

__global__ void __launch_bounds__(256) k_node_pre(const float* __restrict__ x,
                                                  const float* __restrict__ Wpre) {
    extern __shared__ float sm[];
    float* Ws = sm;               // [ci][co], pitch 132
    float* xs = sm + 128*132;     // [ci][r],  pitch 36
    int tid = threadIdx.x;

    for (int idx = tid; idx < CD*CD; idx += 256) {
        int co = idx >> 7, ci = idx & 127;
        Ws[ci*132 + co] = Wpre[co*CAD + ci];
    }

    int lane = tid & 31, warp = tid >> 5;
    for (int tile = blockIdx.x; tile < K1_TILES; tile += gridDim.x) {
        int rowBase = tile*32;
        __syncthreads();
        for (int idx = tid; idx < 32*CD; idx += 256) {
            int r = idx >> 7, ci = idx & 127;
            xs[ci*36 + r] = x[(size_t)(rowBase + r)*CD + ci];
        }
        __syncthreads();

        ull acc2[4][2];
#pragma unroll
        for (int r = 0; r < 4; ++r) { acc2[r][0] = 0ull; acc2[r][1] = 0ull; }

#pragma unroll 8
        for (int ci = 0; ci < CD; ++ci) {
            float4 xv = *(const float4*)&xs[ci*36  + warp*4];
            const ulonglong2* wp = (const ulonglong2*)&Ws[ci*132 + lane*4];
            ulonglong2 w = *wp;
            ull xd;
            xd = pack2(xv.x, xv.x); ffma2(acc2[0][0], xd, w.x); ffma2(acc2[0][1], xd, w.y);
            xd = pack2(xv.y, xv.y); ffma2(acc2[1][0], xd, w.x); ffma2(acc2[1][1], xd, w.y);
            xd = pack2(xv.z, xv.z); ffma2(acc2[2][0], xd, w.x); ffma2(acc2[2][1], xd, w.y);
            xd = pack2(xv.w, xv.w); ffma2(acc2[3][0], xd, w.x); ffma2(acc2[3][1], xd, w.y);
        }
#pragma unroll
        for (int r = 0; r < 4; ++r) {
            float4 o4;
            unpack2(acc2[r][0], o4.x, o4.y);
            unpack2(acc2[r][1], o4.z, o4.w);
            *(float4*)&g_y[(size_t)(rowBase + warp*4 + r)*CD + lane*4] = o4;
        }
    }
}

// ---------------------------------------------------------------------------
// K2: gather kernel. One CTA per destination node, 128 threads.
//   Thread owns channel c = tid, computes all 12 orientations.
//   Edge data staged via 3-deep cp.async pipeline (144 x 16B per edge).
// ---------------------------------------------------------------------------
#define DEPTH 3

__global__ void __launch_bounds__(128) k_gather(const float* __restrict__ kb,
                                                const float* __restrict__ attr,
                                                const float* __restrict__ Wpre,
                                                const float* __restrict__ Wk) {
    // per stage: [0:384) kb (o*32+k), [384:576) attr (o*16+a) — 2304B
    __shared__ __align__(16) float sbuf[DEPTH][576];

    int tid = threadIdx.x;          // channel c
    int c = tid;

    // per-channel weight pairs in registers
    ull wk2[KD/2], wa2[AD/2];
    {
        const float2* wkp = (const float2*)(Wk + (size_t)c*KD);
#pragma unroll
        for (int i = 0; i < KD/2; ++i) { float2 v = wkp[i]; wk2[i] = pack2(v.x, v.y); }
        const float2* wap = (const float2*)(Wpre + (size_t)c*CAD + CD);
#pragma unroll
        for (int i = 0; i < AD/2; ++i) { float2 v = wap[i]; wa2[i] = pack2(v.x, v.y); }
    }

    int n   = blockIdx.x;
    int r0  = g_off[n];
    int cnt = g_cnt[n];
    int r1  = r0 + cnt;

    float acc[OD];
#pragma unroll
    for (int o = 0; o < OD; ++o) acc[o] = 0.f;

    // ---- stage issuer: fetch edge at CSR slot 'it' into stage s (maybe empty) ----
    // chunks: 0..95 kb (16B each), 96..143 attr. thread t does chunk t, t<16 also 128+t.
    auto issue_stage = [&](int it, int s) {
        if (it < r1) {
            int e = g_elist[it] & 0x1FFFF;
            const char* kbe = (const char*)(kb   + (size_t)e*384);
            const char* ate = (const char*)(attr + (size_t)e*192);
            unsigned sb = (unsigned)__cvta_generic_to_shared(&sbuf[s][0]);
            const char* g0 = (tid < 96) ? (kbe + tid*16) : (ate + (tid - 96)*16);
            cp_async16(sb + tid*16, g0);
            if (tid < 16)
                cp_async16(sb + (128 + tid)*16, ate + (32 + tid)*16);
        }
        asm volatile("cp.async.commit_group;" ::: "memory");  // unconditional
    };

    // prologue: stages for first two edges (groups committed even if empty)
    issue_stage(r0,     0);
    issue_stage(r0 + 1, 1);

    for (int it = r0; it < r1; ++it) {
        int s = (it - r0) % DEPTH;
        // current edge's group has arrived when <=1 groups remain pending
        asm volatile("cp.async.wait_group 1;" ::: "memory");
        __syncthreads();   // all threads' portions visible; stage s-1 free for reuse

        // refill: edge it+2 into stage (it+2-r0)%DEPTH (== stage consumed at it-1)
        issue_stage(it + 2, (it + 2 - r0) % DEPTH);

        int pk  = g_elist[it];
        int src = pk >> 17;

        // gather y for all orientations (MLP 12)
        const float* yb = g_y + (size_t)src*(OD*CD) + c;
        float yv[OD];
#pragma unroll
        for (int o = 0; o < OD; ++o) yv[o] = yb[o*CD];

        const float* kbb = sbuf[s];
        const float* atb = sbuf[s] + 384;
#pragma unroll
        for (int o = 0; o < OD; ++o) {
            ull a2 = 0ull;
            const ulonglong2* k2 = (const ulonglong2*)(kbb + o*KD);
#pragma unroll
            for (int q = 0; q < 8; ++q) {
                ulonglong2 v = k2[q];
                ffma2(a2, v.x, wk2[2*q]);
                ffma2(a2, v.y, wk2[2*q+1]);
            }
            ull z2 = 0ull;
            const ulonglong2* t2 = (const ulonglong2*)(atb + o*AD);
#pragma unroll
            for (int q = 0; q < 4; ++q) {
                ulonglong2 v = t2[q];
                ffma2(z2, v.x, wa2[2*q]);
                ffma2(z2, v.y, wa2[2*q+1]);
            }
            float km = hsum2(a2);
            float z  = hsum2(z2);
            acc[o] += (yv[o] + z) * km;
        }
    }
    asm volatile("cp.async.wait_group 0;" ::: "memory");  // drain before exit

#pragma unroll
    for (int o = 0; o < OD; ++o)
        g_x1[(size_t)n*(OD*CD) + o*CD + c] = acc[o];
}

// ---------------------------------------------------------------------------
// K3: out[n,p,c] = (sum_o x1[n,o,c] * fk[p,o,c]) / O + bias[c]
// ---------------------------------------------------------------------------
#define K3_SMEM (OD*OD*CD*4)

__global__ void __launch_bounds__(256) k_fiber(const float* __restrict__ bias,
                                               float* __restrict__ out) {
    extern __shared__ float fks[];
    int tid = threadIdx.x;
    for (int i = tid; i < OD*OD*CD; i += blockDim.x) fks[i] = g_fk[i];
    __syncthreads();
    int c = tid & 127, sub = tid >> 7;
    float bs = bias[c];
    int base = blockIdx.x * 8;
    for (int nn = sub; nn < 8; nn += 2) {
        int n = base + nn;
        if (n >= NN) break;
        float xr[OD];
#pragma unroll
        for (int o = 0; o < OD; ++o)
            xr[o] = g_x1[(size_t)(n*OD + o)*CD + c];
#pragma unroll
        for (int p = 0; p < OD; ++p) {
            float acc = 0.f;
#pragma unroll
            for (int o = 0; o < OD; ++o)
                acc += xr[o] * fks[(p*OD + o)*CD + c];
            out[(size_t)(n*OD + p)*CD + c] = acc * (1.0f/12.0f) + bs;
        }
    }
}

// ---------------------------------------------------------------------------
extern "C" void kernel_launch(void* const* d_in, const int* in_sizes, int n_in,
                              void* d_out, int out_size) {
    (void)out_size;
    // Size-based dispatch. Unique element counts except Wk/Wf (4096, order tiebreak).
    const float *x=0, *kb=0, *fkb=0, *attr=0, *Wpre=0, *Wk=0, *Wf=0, *bias=0;
    const int* eidx = 0;
    for (int i = 0; i < n_in; ++i) {
        switch (in_sizes[i]) {
            case 15360000: x    = (const float*)d_in[i]; break;
            case 38400000: kb   = (const float*)d_in[i]; break;
            case 4608:     fkb  = (const float*)d_in[i]; break;
            case 200000:   eidx = (const int*)  d_in[i]; break;
            case 19200000: attr = (const float*)d_in[i]; break;
            case 18432:    Wpre = (const float*)d_in[i]; break;
            case 4096:     if (!Wk) Wk = (const float*)d_in[i];
                           else     Wf = (const float*)d_in[i]; break;
            case 128:      bias = (const float*)d_in[i]; break;
            default: break;
        }
    }
    float* out = (float*)d_out;

    cudaFuncSetAttribute(k_node_pre, cudaFuncAttributeMaxDynamicSharedMemorySize, K1_SMEM);
    cudaFuncSetAttribute(k_fiber,    cudaFuncAttributeMaxDynamicSharedMemorySize, K3_SMEM);

    k_zero_cnt <<<(NN + 255)/256, 256>>>();
    k_count    <<<256, 256>>>(eidx);
    k_scan     <<<1, 1024>>>();
    k_fill     <<<256, 256>>>(eidx);
    k_fiber_pre<<<OD*OD, CD>>>(fkb, Wf);
    k_node_pre <<<592, 256, K1_SMEM>>>(x, Wpre);
    k_gather   <<<NN, 128>>>(kb, attr, Wpre, Wk);
    k_fiber    <<<(NN + 7)/8, 256, K3_SMEM>>>(bias, out);
}